// round 7
// baseline (speedup 1.0000x reference)
#include <cuda_runtime.h>
#include <math.h>

#define BB     1024
#define HH     256
#define FOURH  1024
#define LAT    128
#define ROWS   7
#define NCTA   147              // 147*7 = 1029 >= 1024 (last CTA partially masked)
#define NT     512              // (j, s): j = t & 255 owns H-column, s = t >> 8 owns k-half
#define KHALF  128
#define GSIZE  64
#define EPSG   1e-5f

typedef unsigned long long u64;

// -------- device scratch --------
// Gate-interleaved, k-major transposed weights: [k][j] float4 = W[(g*H+j),k], g=i,f,g,o
__device__ float4 g_Wt0 [HH * HH];   // Whh0^T
__device__ float4 g_Wt1i[HH * HH];   // Wih1^T
__device__ float4 g_Wt1h[HH * HH];   // Whh1^T
__device__ float  g_Wut [LAT * HH];  // W_unpack^T [k][j]

__device__ __forceinline__ float tanh_fast(float x) {
    float y; asm("tanh.approx.f32 %0, %1;" : "=f"(y) : "f"(x)); return y;
}
__device__ __forceinline__ float sig_fast(float x) {
    return 0.5f * tanh_fast(0.5f * x) + 0.5f;
}
__device__ __forceinline__ u64 pack2(float lo, float hi) {
    u64 r; asm("mov.b64 %0, {%1, %2};" : "=l"(r) : "f"(lo), "f"(hi)); return r;
}
__device__ __forceinline__ void unpack2(u64 v, float& lo, float& hi) {
    asm("mov.b64 {%0, %1}, %2;" : "=f"(lo), "=f"(hi) : "l"(v));
}
__device__ __forceinline__ u64 fma2(u64 a, u64 b, u64 c) {
    u64 d; asm("fma.rn.f32x2 %0, %1, %2, %3;" : "=l"(d) : "l"(a), "l"(b), "l"(c)); return d;
}
__device__ __forceinline__ u64 add2(u64 a, u64 b) {
    u64 d; asm("add.rn.f32x2 %0, %1, %2;" : "=l"(d) : "l"(a), "l"(b)); return d;
}
__device__ __forceinline__ void ldg_v2u64(const void* p, u64& a, u64& b) {
    asm("ld.global.nc.v2.u64 {%0, %1}, [%2];" : "=l"(a), "=l"(b) : "l"(p));
}

// -------- prologue: transpose weights --------
__global__ void prep_kernel(const float* __restrict__ Whh0,
                            const float* __restrict__ Wih1,
                            const float* __restrict__ Whh1,
                            const float* __restrict__ Wu) {
    int i = blockIdx.x * blockDim.x + threadIdx.x;
    if (i < HH * FOURH) {
        int k   = i >> 10;
        int rem = i & 1023;
        int j   = rem >> 2;
        int g   = rem & 3;
        int src = (g * HH + j) * HH + k;
        ((float*)g_Wt0)[i]  = Whh0[src];
        ((float*)g_Wt1i)[i] = Wih1[src];
        ((float*)g_Wt1h)[i] = Whh1[src];
    }
    if (i < LAT * HH) {
        int k = i >> 8, j = i & 255;
        g_Wut[i] = Wu[j * LAT + k];
    }
}

// -------- main persistent kernel --------
__global__ __launch_bounds__(NT, 1)
void gen_kernel(const float* __restrict__ noise,
                const float* __restrict__ b_unpack,
                const float* __restrict__ Wih0,
                const float* __restrict__ bih0, const float* __restrict__ bhh0,
                const float* __restrict__ bih1, const float* __restrict__ bhh1,
                const float* __restrict__ gamma_a, const float* __restrict__ beta_a,
                const float* __restrict__ Wa, const float* __restrict__ ba,
                const float* __restrict__ gamma_w, const float* __restrict__ beta_w,
                const float* __restrict__ Ww, const float* __restrict__ bw,
                int T, float* __restrict__ out) {
    // h duplicated per element as (h,h) u64: [k][r] (row dim padded to 8)
    __shared__ __align__(16) u64 sh0d[HH][8];      // 16KB
    __shared__ __align__(16) u64 sh1d[HH][8];      // 16KB
    __shared__ __align__(16) u64 red[HH][17];      // ~34KB, k-split partials
    __shared__ float sh1n[ROWS][HH];               // 7KB
    __shared__ float sGA[HH], sBA[HH], sGW[HH], sBW[HH];
    __shared__ float sStat[ROWS][4][2];
    __shared__ float scoord[ROWS][2];

    const int t    = threadIdx.x;
    const int j    = t & (HH - 1);     // H-column
    const int s    = t >> 8;           // k-half
    const int r0   = blockIdx.x * ROWS;
    const int warp = t >> 5;
    const int lane = t & 31;

    if (s == 0) {
        float wav = Wa[j], wwv = Ww[j];
        sGA[j] = gamma_a[j] * wav;  sBA[j] = beta_a[j] * wav;
        sGW[j] = gamma_w[j] * wwv;  sBW[j] = beta_w[j] * wwv;
    }
    const float bav = ba[0], bwv = bw[0];

    // Per-thread packed gate constants (pairs 01=(i,f), 23=(g,o)); used by s==0
    u64 bias0_01, bias0_23, bias1_01, bias1_23;
    u64 wi0a_01, wi0a_23, wi0b_01, wi0b_23;
    {
        float b0[4], b1[4], wa[4], wb[4];
#pragma unroll
        for (int g = 0; g < 4; g++) {
            int n = g * HH + j;
            b0[g] = bih0[n] + bhh0[n];
            b1[g] = bih1[n] + bhh1[n];
            wa[g] = Wih0[n * 2 + 0];
            wb[g] = Wih0[n * 2 + 1];
        }
        bias0_01 = pack2(b0[0], b0[1]); bias0_23 = pack2(b0[2], b0[3]);
        bias1_01 = pack2(b1[0], b1[1]); bias1_23 = pack2(b1[2], b1[3]);
        wi0a_01  = pack2(wa[0], wa[1]); wi0a_23  = pack2(wa[2], wa[3]);
        wi0b_01  = pack2(wb[0], wb[1]); wi0b_23  = pack2(wb[2], wb[3]);
    }

    // Stage noise (alias red as scratch); clamp row index for padding rows
    float* snoise = (float*)red;
    for (int i = t; i < ROWS * LAT; i += NT) {
        int rr = i / LAT, kk = i - rr * LAT;
        int src_row = min(r0 + rr, BB - 1);
        snoise[i] = noise[(size_t)src_row * LAT + kk];
    }
    if (t < ROWS * 2) ((float*)scoord)[t] = 0.f;
    __syncthreads();

    // idea = elu(noise @ W_unpack^T + b_unpack); s==0 only (one-time)
    float c0r[ROWS], c1r[ROWS];
    if (s == 0) {
        float acc[ROWS];
        float bu = b_unpack[j];
#pragma unroll
        for (int r = 0; r < ROWS; r++) acc[r] = bu;
        for (int k = 0; k < LAT; k++) {
            float w = g_Wut[k * HH + j];
#pragma unroll
            for (int r = 0; r < ROWS; r++) acc[r] = fmaf(snoise[r * LAT + k], w, acc[r]);
        }
#pragma unroll
        for (int r = 0; r < ROWS; r++) {
            float v = acc[r];
            float e = (v > 0.f) ? v : (expf(v) - 1.f);
            sh0d[j][r] = pack2(e, e);
            c0r[r] = e;
            sh1d[j][r] = 0ull;
            sh1n[r][j] = 0.f;
            c1r[r] = 0.f;
        }
        // pad row 7 so vector LDS of rows 6-7 reads defined data
        sh0d[j][7] = 0ull;
        sh1d[j][7] = 0ull;
    }
    __syncthreads();

    // Weight pointers offset by this thread's k-half
    const float4* __restrict__ w0  = g_Wt0  + (size_t)(s * KHALF) * HH + j;
    const float4* __restrict__ w1i = g_Wt1i + (size_t)(s * KHALF) * HH + j;
    const float4* __restrict__ w1h = g_Wt1h + (size_t)(s * KHALF) * HH + j;
    const int kbase = s * KHALF;

    for (int step = 0; step < T; ++step) {
        // ================= layer 0 partials =================
        u64 a01[ROWS], a23[ROWS];
        if (s == 0) {
#pragma unroll
            for (int r = 0; r < ROWS; r++) {
                u64 cx = pack2(scoord[r][0], scoord[r][0]);
                u64 cy = pack2(scoord[r][1], scoord[r][1]);
                a01[r] = fma2(wi0a_01, cx, fma2(wi0b_01, cy, bias0_01));
                a23[r] = fma2(wi0a_23, cx, fma2(wi0b_23, cy, bias0_23));
            }
        } else {
#pragma unroll
            for (int r = 0; r < ROWS; r++) { a01[r] = 0ull; a23[r] = 0ull; }
        }
#pragma unroll 8
        for (int k = 0; k < KHALF; k++) {
            u64 w01, w23;
            ldg_v2u64(&w0[k * HH], w01, w23);
            const u64* hrow = sh0d[kbase + k];
            ulonglong2 h0 = *(const ulonglong2*)&hrow[0];
            ulonglong2 h1 = *(const ulonglong2*)&hrow[2];
            ulonglong2 h2 = *(const ulonglong2*)&hrow[4];
            u64 h6 = hrow[6];
            u64 h[ROWS] = {h0.x, h0.y, h1.x, h1.y, h2.x, h2.y, h6};
#pragma unroll
            for (int r = 0; r < ROWS; r++) {
                a01[r] = fma2(w01, h[r], a01[r]);
                a23[r] = fma2(w23, h[r], a23[r]);
            }
        }
        if (s == 1) {
#pragma unroll
            for (int r = 0; r < ROWS; r++) {
                red[j][r]     = a01[r];
                red[j][8 + r] = a23[r];
            }
        }
        __syncthreads();                        // (A) partials ready, L0 reads done
        if (s == 0) {
#pragma unroll
            for (int r = 0; r < ROWS; r++) {
                float gi, gf, gg, go;
                unpack2(add2(a01[r], red[j][r]),     gi, gf);
                unpack2(add2(a23[r], red[j][8 + r]), gg, go);
                float cn = fmaf(sig_fast(gf), c0r[r], sig_fast(gi) * tanh_fast(gg));
                c0r[r]   = cn;
                float hn = sig_fast(go) * tanh_fast(cn);
                sh0d[j][r] = pack2(hn, hn);
            }
        }
        __syncthreads();                        // (B) new sh0d visible

        // ================= layer 1 partials =================
        if (s == 0) {
#pragma unroll
            for (int r = 0; r < ROWS; r++) { a01[r] = bias1_01; a23[r] = bias1_23; }
        } else {
#pragma unroll
            for (int r = 0; r < ROWS; r++) { a01[r] = 0ull; a23[r] = 0ull; }
        }
#pragma unroll 4
        for (int k = 0; k < KHALF; k++) {
            u64 wi01, wi23, wh01, wh23;
            ldg_v2u64(&w1i[k * HH], wi01, wi23);
            ldg_v2u64(&w1h[k * HH], wh01, wh23);
            const u64* prow = sh0d[kbase + k];
            const u64* qrow = sh1d[kbase + k];
            ulonglong2 p0 = *(const ulonglong2*)&prow[0];
            ulonglong2 p1 = *(const ulonglong2*)&prow[2];
            ulonglong2 p2 = *(const ulonglong2*)&prow[4];
            u64 p6 = prow[6];
            ulonglong2 q0 = *(const ulonglong2*)&qrow[0];
            ulonglong2 q1 = *(const ulonglong2*)&qrow[2];
            ulonglong2 q2 = *(const ulonglong2*)&qrow[4];
            u64 q6 = qrow[6];
            u64 ha[ROWS] = {p0.x, p0.y, p1.x, p1.y, p2.x, p2.y, p6};
            u64 hb[ROWS] = {q0.x, q0.y, q1.x, q1.y, q2.x, q2.y, q6};
#pragma unroll
            for (int r = 0; r < ROWS; r++) {
                a01[r] = fma2(wi01, ha[r], fma2(wh01, hb[r], a01[r]));
                a23[r] = fma2(wi23, ha[r], fma2(wh23, hb[r], a23[r]));
            }
        }
        if (s == 1) {
#pragma unroll
            for (int r = 0; r < ROWS; r++) {
                red[j][r]     = a01[r];
                red[j][8 + r] = a23[r];
            }
        }
        __syncthreads();                        // (C)
        if (s == 0) {
#pragma unroll
            for (int r = 0; r < ROWS; r++) {
                float gi, gf, gg, go;
                unpack2(add2(a01[r], red[j][r]),     gi, gf);
                unpack2(add2(a23[r], red[j][8 + r]), gg, go);
                float cn = fmaf(sig_fast(gf), c1r[r], sig_fast(gi) * tanh_fast(gg));
                c1r[r]   = cn;
                float hn = sig_fast(go) * tanh_fast(cn);
                sh1d[j][r] = pack2(hn, hn);
                sh1n[r][j] = hn;
            }
        }
        __syncthreads();                        // (D) sh1n visible

        // ================= GroupNorm stats (warps 0-6 -> rows 0-6) =============
        if (warp < ROWS) {
            int r = warp;
#pragma unroll
            for (int g = 0; g < 4; g++) {
                float v0 = sh1n[r][g * GSIZE + lane];
                float v1 = sh1n[r][g * GSIZE + 32 + lane];
                float sm = v0 + v1, q = fmaf(v0, v0, v1 * v1);
#pragma unroll
                for (int off = 16; off; off >>= 1) {
                    sm += __shfl_xor_sync(0xffffffffu, sm, off);
                    q  += __shfl_xor_sync(0xffffffffu, q,  off);
                }
                if (lane == 0) {
                    float mu  = sm * (1.f / GSIZE);
                    float var = q * (1.f / GSIZE) - mu * mu;
                    sStat[r][g][0] = mu;
                    sStat[r][g][1] = rsqrtf(var + EPSG);
                }
            }
        }
        __syncthreads();                        // (E)

        // ================= heads =================
        if (warp < ROWS) {
            int r = warp;
            float aacc = 0.f, wacc = 0.f;
#pragma unroll
            for (int jj = 0; jj < HH; jj += 32) {
                int jx = jj + lane;
                int g  = jj >> 6;
                float xn = (sh1n[r][jx] - sStat[r][g][0]) * sStat[r][g][1];
                aacc += fmaf(xn, sGA[jx], sBA[jx]);
                wacc += fmaf(xn, sGW[jx], sBW[jx]);
            }
#pragma unroll
            for (int off = 16; off; off >>= 1) {
                aacc += __shfl_xor_sync(0xffffffffu, aacc, off);
                wacc += __shfl_xor_sync(0xffffffffu, wacc, off);
            }
            if (lane == 0) {
                float ang = tanh_fast(aacc + bav);
                float wid = sig_fast(wacc + bwv);
                scoord[r][0] = ang;
                scoord[r][1] = wid;
                if (r0 + r < BB) {
                    float2* op = (float2*)(out + ((size_t)(r0 + r) * T + step) * 2);
                    *op = make_float2(ang, wid);
                }
            }
        }
        __syncthreads();                        // (F) scoord visible next step
    }
}

extern "C" void kernel_launch(void* const* d_in, const int* in_sizes, int n_in,
                              void* d_out, int out_size) {
    const float* noise    = (const float*)d_in[0];
    const float* W_unpack = (const float*)d_in[1];
    const float* b_unpack = (const float*)d_in[2];
    const float* Wih0     = (const float*)d_in[3];
    const float* Whh0     = (const float*)d_in[4];
    const float* bih0     = (const float*)d_in[5];
    const float* bhh0     = (const float*)d_in[6];
    const float* Wih1     = (const float*)d_in[7];
    const float* Whh1     = (const float*)d_in[8];
    const float* bih1     = (const float*)d_in[9];
    const float* bhh1     = (const float*)d_in[10];
    const float* gamma_a  = (const float*)d_in[11];
    const float* beta_a   = (const float*)d_in[12];
    const float* Wa       = (const float*)d_in[13];
    const float* ba       = (const float*)d_in[14];
    const float* gamma_w  = (const float*)d_in[15];
    const float* beta_w   = (const float*)d_in[16];
    const float* Ww       = (const float*)d_in[17];
    const float* bw       = (const float*)d_in[18];
    (void)in_sizes; (void)n_in;

    int T = out_size / (BB * 2);

    prep_kernel<<<(HH * FOURH + 255) / 256, 256>>>(Whh0, Wih1, Whh1, W_unpack);
    gen_kernel<<<NCTA, NT>>>(noise, b_unpack, Wih0, bih0, bhh0, bih1, bhh1,
                             gamma_a, beta_a, Wa, ba, gamma_w, beta_w, Ww, bw,
                             T, (float*)d_out);
}

// round 9
// speedup vs baseline: 2.4237x; 2.4237x over previous
#include <cuda_runtime.h>
#include <cuda_fp16.h>
#include <math.h>
#include <cstdint>

typedef unsigned long long u64;
typedef unsigned int u32;

#define BB 1024
#define TILES 8
#define NT 256
#define NCTA 128
#define EPSG 1e-5f

#define A_OFF  0          // 32 k-chunks * 4096B (chunks 0-15: h0, 16-31: h1)
#define B0_OFF 131072     // 32KB  L0 weight frags
#define B1_OFF 163840     // 64KB  L1 weight frags
#define HC_OFF 229376     // 2KB   head consts (4 x 256 half)
#define SC_OFF 231424     // 1KB   coords (128 float2)
#define SMEM_TOTAL 232448

// ---------------- global scratch ----------------
__device__ u64 g_frag0[16 * 4096];   // [q][c16][ntp4][lane32][2]
__device__ u64 g_frag1[16 * 8192];   // [q][c32][ntp4][lane32][2]
__device__ float4 g_epi[256 * 4];    // [j][bias0|wa|wb|bias1] per-gate float4
__device__ float  g_Wup[128 * 256];
__device__ float  g_hA1[256], g_hA0[256], g_hW1[256], g_hW0[256];
__device__ __half g_h0[TILES * 128 * 256];
__device__ __half g_h1[TILES * 128 * 256];
__device__ float  g_h0f[TILES * 128 * 256];
__device__ unsigned g_barc[TILES];

__device__ __forceinline__ float tanh_fast(float x) {
    float y; asm("tanh.approx.f32 %0, %1;" : "=f"(y) : "f"(x)); return y;
}
__device__ __forceinline__ float sig_fast(float x) {
    return 0.5f * tanh_fast(0.5f * x) + 0.5f;
}
__device__ __forceinline__ u32 smem_u32_of(const void* p) {
    u32 a;
    asm("{ .reg .u64 t; cvta.to.shared.u64 t, %1; cvt.u32.u64 %0, t; }" : "=r"(a) : "l"(p));
    return a;
}
#define CP16(dst, src) \
    asm volatile("cp.async.cg.shared.global [%0], [%1], 16;" :: "r"(dst), "l"(src))
#define CP_COMMIT()  asm volatile("cp.async.commit_group;" ::: "memory")
#define CP_WAITALL() asm volatile("cp.async.wait_all;" ::: "memory")

__device__ __forceinline__ void mma16816(float* d, u32 a0, u32 a1, u32 a2, u32 a3,
                                         u32 b0, u32 b1) {
    asm volatile(
        "mma.sync.aligned.m16n8k16.row.col.f32.f16.f16.f32 "
        "{%0,%1,%2,%3}, {%4,%5,%6,%7}, {%8,%9}, {%0,%1,%2,%3};"
        : "+f"(d[0]), "+f"(d[1]), "+f"(d[2]), "+f"(d[3])
        : "r"(a0), "r"(a1), "r"(a2), "r"(a3), "r"(b0), "r"(b1));
}

__device__ __forceinline__ void gbar(int tile, unsigned target) {
    __syncthreads();
    if (threadIdx.x == 0) {
        __threadfence();
        atomicAdd(&g_barc[tile], 1u);
        unsigned v;
        do {
            asm volatile("ld.acquire.gpu.global.u32 %0, [%1];" : "=r"(v) : "l"(&g_barc[tile]));
            if (v < target) __nanosleep(64);
        } while (v < target);
    }
    __syncthreads();
}

__device__ __forceinline__ u64 pack_frag(const float* wr, int k0) {
    __half a = __float2half(wr[k0]),     b = __float2half(wr[k0 + 1]);
    __half c = __float2half(wr[k0 + 8]), d = __float2half(wr[k0 + 9]);
    return (u64)__half_as_ushort(a) | ((u64)__half_as_ushort(b) << 16)
         | ((u64)__half_as_ushort(c) << 32) | ((u64)__half_as_ushort(d) << 48);
}

// ---------------- prep ----------------
__global__ void prep_kernel(const float* __restrict__ W_unpack,
                            const float* __restrict__ Wih0,
                            const float* __restrict__ Whh0,
                            const float* __restrict__ bih0, const float* __restrict__ bhh0,
                            const float* __restrict__ Wih1,
                            const float* __restrict__ Whh1,
                            const float* __restrict__ bih1, const float* __restrict__ bhh1,
                            const float* __restrict__ gamma_a, const float* __restrict__ beta_a,
                            const float* __restrict__ Wa,
                            const float* __restrict__ gamma_w, const float* __restrict__ beta_w,
                            const float* __restrict__ Ww) {
    int i = blockIdx.x * blockDim.x + threadIdx.x;
    if (i < 65536) {   // L0 frags
        int q = i >> 12, c = (i >> 8) & 15, ntp = (i >> 6) & 3, lane = (i >> 1) & 31, hs = i & 1;
        int nt = ntp * 2 + hs;
        int nloc = nt * 8 + (lane >> 2);
        int j, gate;
        if (nloc < 32) { j = nloc >> 1; gate = (nloc & 1) ? 1 : 0; }
        else { j = (nloc - 32) >> 1; gate = (nloc & 1) ? 3 : 2; }
        int orig = gate * 256 + q * 16 + j;
        g_frag0[i] = pack_frag(Whh0 + orig * 256, c * 16 + (lane & 3) * 2);
    }
    if (i < 131072) {  // L1 frags: chunks 0-15 Wih1, 16-31 Whh1
        int q = i >> 13, c = (i >> 8) & 31, ntp = (i >> 6) & 3, lane = (i >> 1) & 31, hs = i & 1;
        int nt = ntp * 2 + hs;
        int nloc = nt * 8 + (lane >> 2);
        int j, gate;
        if (nloc < 32) { j = nloc >> 1; gate = (nloc & 1) ? 1 : 0; }
        else { j = (nloc - 32) >> 1; gate = (nloc & 1) ? 3 : 2; }
        int orig = gate * 256 + q * 16 + j;
        const float* src = (c < 16) ? Wih1 : Whh1;
        g_frag1[i] = pack_frag(src + orig * 256, (c & 15) * 16 + (lane & 3) * 2);
    }
    if (i < 1024) {
        int j = i >> 2, comp = i & 3;
        float4 v;
        if (comp == 0)
            v = make_float4(bih0[j] + bhh0[j], bih0[256 + j] + bhh0[256 + j],
                            bih0[512 + j] + bhh0[512 + j], bih0[768 + j] + bhh0[768 + j]);
        else if (comp == 1)
            v = make_float4(Wih0[j * 2], Wih0[(256 + j) * 2],
                            Wih0[(512 + j) * 2], Wih0[(768 + j) * 2]);
        else if (comp == 2)
            v = make_float4(Wih0[j * 2 + 1], Wih0[(256 + j) * 2 + 1],
                            Wih0[(512 + j) * 2 + 1], Wih0[(768 + j) * 2 + 1]);
        else
            v = make_float4(bih1[j] + bhh1[j], bih1[256 + j] + bhh1[256 + j],
                            bih1[512 + j] + bhh1[512 + j], bih1[768 + j] + bhh1[768 + j]);
        g_epi[i] = v;
    }
    if (i < 128 * 256) {
        int k = i >> 8, j = i & 255;
        g_Wup[i] = W_unpack[j * 128 + k];
    }
    if (i < 256) {
        g_hA1[i] = gamma_a[i] * Wa[i];  g_hA0[i] = beta_a[i] * Wa[i];
        g_hW1[i] = gamma_w[i] * Ww[i];  g_hW0[i] = beta_w[i] * Ww[i];
    }
    if (i < TILES) g_barc[i] = 0u;
}

// ---------------- main ----------------
__global__ __launch_bounds__(NT, 1)
void gen_kernel(const float* __restrict__ noise,
                const float* __restrict__ b_unpack,
                const float* __restrict__ ba, const float* __restrict__ bw,
                int T, float* __restrict__ out) {
    extern __shared__ char smem[];
    const u32 sbase = smem_u32_of(smem);
    const int t = threadIdx.x;
    const int w = t >> 5, lane = t & 31;
    const int tile = blockIdx.x >> 4;
    const int q = blockIdx.x & 15;
    const int m0 = w * 16;
    float2* sc = (float2*)(smem + SC_OFF);
    const float bav = __ldg(ba), bwv = __ldg(bw);

    // head consts -> SMEM (half)
    {
        __half* hc = (__half*)(smem + HC_OFF);
        hc[t]       = __float2half(g_hA1[t]);
        hc[256 + t] = __float2half(g_hA0[t]);
        hc[512 + t] = __float2half(g_hW1[t]);
        hc[768 + t] = __float2half(g_hW0[t]);
        ((float*)sc)[t] = 0.f;   // 256 floats = 128 float2
    }

    // weights -> SMEM (already fragment-ordered)
    for (int u = t; u < 2048; u += NT)
        CP16(sbase + B0_OFF + u * 16, (const char*)(g_frag0 + q * 4096) + u * 16);
    for (int u = t; u < 4096; u += NT)
        CP16(sbase + B1_OFF + u * 16, (const char*)(g_frag1 + q * 8192) + u * 16);
    CP_COMMIT();

    // noise into A area (scratch floats), then idea GEMV (slice's 16 j cols)
    float* nf = (float*)(smem + A_OFF);
    for (int i = t; i < 128 * 128; i += NT)
        nf[i] = __ldg(&noise[(size_t)(tile * 128) * 128 + i]);
    __syncthreads();
    if (t < 128) {
        float acc[16];
#pragma unroll
        for (int j = 0; j < 16; j++) acc[j] = __ldg(&b_unpack[q * 16 + j]);
        for (int k = 0; k < 128; k++) {
            float nv = nf[t * 128 + k];
            const float* wr = &g_Wup[k * 256 + q * 16];
#pragma unroll
            for (int j = 0; j < 16; j++) acc[j] = fmaf(nv, __ldg(&wr[j]), acc[j]);
        }
#pragma unroll
        for (int j = 0; j < 16; j++) {
            float v = acc[j];
            float e = (v > 0.f) ? v : (expf(v) - 1.f);
            size_t gi = (size_t)(tile * 128 + t) * 256 + q * 16 + j;
            unsigned short hs = __half_as_ushort(__float2half(e));
            asm volatile("st.global.cg.u16 [%0], %1;" :: "l"(&g_h0[gi]), "h"(hs));
            asm volatile("st.global.cg.f32 [%0], %1;" :: "l"(&g_h0f[gi]), "f"(e));
        }
    }
    CP_WAITALL();
    unsigned bt = 16;
    gbar(tile, bt);

    // c-state init from fp32 idea at this thread's (m, j) cells
    float c0s[2][4], c1s[2][4];
    {
        int r1 = m0 + (lane >> 2);
#pragma unroll
        for (int tt = 0; tt < 4; tt++) {
            int jg = q * 16 + 4 * tt + (lane & 3);
            c0s[0][tt] = g_h0f[(size_t)(tile * 128 + r1) * 256 + jg];
            c0s[1][tt] = g_h0f[(size_t)(tile * 128 + r1 + 8) * 256 + jg];
            c1s[0][tt] = 0.f; c1s[1][tt] = 0.f;
        }
    }
    // A chunks 0-15 <- h0 (swizzled), 16-31 <- 0
    for (int u = t; u < 4096; u += NT) {
        int c = u >> 8, rem = u & 255, m = rem >> 1, hi = rem & 1;
        u32 dst = sbase + A_OFF + c * 4096 + m * 32 + (((hi ^ (m >> 2)) & 1) << 4);
        CP16(dst, &g_h0[(size_t)(tile * 128 + m) * 256 + c * 16 + hi * 8]);
    }
    CP_COMMIT();
    {
        uint4 z = make_uint4(0, 0, 0, 0);
        uint4* az = (uint4*)(smem + A_OFF + 65536);
        for (int i = t; i < 4096; i += NT) az[i] = z;
    }
    CP_WAITALL();
    __syncthreads();

    const u32 aBase = sbase + A_OFF + (m0 + (lane & 15)) * 32 +
                      (((lane >> 4) ^ (((lane & 15) >> 2) & 1)) << 4);
    const int r1 = m0 + (lane >> 2);

    for (int step = 0; step < T; ++step) {
        float d[8][4];
        // ===== L0 MMA: K=256 (chunks 0-15) =====
#pragma unroll
        for (int n = 0; n < 8; n++) { d[n][0]=d[n][1]=d[n][2]=d[n][3]=0.f; }
#pragma unroll
        for (int c = 0; c < 16; c++) {
            u32 a0, a1, a2, a3;
            asm volatile("ldmatrix.sync.aligned.m8n8.x4.shared.b16 {%0,%1,%2,%3}, [%4];"
                         : "=r"(a0), "=r"(a1), "=r"(a2), "=r"(a3) : "r"(aBase + c * 4096));
#pragma unroll
            for (int p = 0; p < 4; p++) {
                u32 b0, b1, b2, b3;
                asm volatile("ld.shared.v4.b32 {%0,%1,%2,%3}, [%4];"
                             : "=r"(b0), "=r"(b1), "=r"(b2), "=r"(b3)
                             : "r"(sbase + B0_OFF + (c * 4 + p) * 512 + lane * 16));
                mma16816(d[p * 2],     a0, a1, a2, a3, b0, b1);
                mma16816(d[p * 2 + 1], a0, a1, a2, a3, b2, b3);
            }
        }
        // ===== L0 epilogue =====
        {
            float2 cdA = sc[r1], cdB = sc[r1 + 8];
#pragma unroll
            for (int tt = 0; tt < 4; tt++) {
                int jg = q * 16 + 4 * tt + (lane & 3);
                float4 e0 = __ldg(&g_epi[jg * 4 + 0]);
                float4 ea = __ldg(&g_epi[jg * 4 + 1]);
                float4 eb = __ldg(&g_epi[jg * 4 + 2]);
#pragma unroll
                for (int ri = 0; ri < 2; ri++) {
                    float2 cd = ri ? cdB : cdA;
                    float gi = d[tt][2*ri]   + e0.x + ea.x * cd.x + eb.x * cd.y;
                    float gf = d[tt][2*ri+1] + e0.y + ea.y * cd.x + eb.y * cd.y;
                    float gg = d[tt+4][2*ri]   + e0.z + ea.z * cd.x + eb.z * cd.y;
                    float go = d[tt+4][2*ri+1] + e0.w + ea.w * cd.x + eb.w * cd.y;
                    float cn = fmaf(sig_fast(gf), c0s[ri][tt], sig_fast(gi) * tanh_fast(gg));
                    c0s[ri][tt] = cn;
                    unsigned short hs = __half_as_ushort(__float2half(sig_fast(go) * tanh_fast(cn)));
                    asm volatile("st.global.cg.u16 [%0], %1;"
                        :: "l"(&g_h0[(size_t)(tile * 128 + r1 + 8 * ri) * 256 + jg]), "h"(hs));
                }
            }
        }
        bt += 16; gbar(tile, bt);
        for (int u = t; u < 4096; u += NT) {       // reload h0 -> chunks 0-15
            int c = u >> 8, rem = u & 255, m = rem >> 1, hi = rem & 1;
            u32 dst = sbase + A_OFF + c * 4096 + m * 32 + (((hi ^ (m >> 2)) & 1) << 4);
            CP16(dst, &g_h0[(size_t)(tile * 128 + m) * 256 + c * 16 + hi * 8]);
        }
        CP_COMMIT(); CP_WAITALL();
        __syncthreads();

        // ===== L1 MMA: K=512 (chunks 0-31) =====
#pragma unroll
        for (int n = 0; n < 8; n++) { d[n][0]=d[n][1]=d[n][2]=d[n][3]=0.f; }
#pragma unroll
        for (int c = 0; c < 32; c++) {
            u32 a0, a1, a2, a3;
            asm volatile("ldmatrix.sync.aligned.m8n8.x4.shared.b16 {%0,%1,%2,%3}, [%4];"
                         : "=r"(a0), "=r"(a1), "=r"(a2), "=r"(a3) : "r"(aBase + c * 4096));
#pragma unroll
            for (int p = 0; p < 4; p++) {
                u32 b0, b1, b2, b3;
                asm volatile("ld.shared.v4.b32 {%0,%1,%2,%3}, [%4];"
                             : "=r"(b0), "=r"(b1), "=r"(b2), "=r"(b3)
                             : "r"(sbase + B1_OFF + (c * 4 + p) * 512 + lane * 16));
                mma16816(d[p * 2],     a0, a1, a2, a3, b0, b1);
                mma16816(d[p * 2 + 1], a0, a1, a2, a3, b2, b3);
            }
        }
        // ===== L1 epilogue =====
        {
#pragma unroll
            for (int tt = 0; tt < 4; tt++) {
                int jg = q * 16 + 4 * tt + (lane & 3);
                float4 e3 = __ldg(&g_epi[jg * 4 + 3]);
#pragma unroll
                for (int ri = 0; ri < 2; ri++) {
                    float gi = d[tt][2*ri] + e3.x;
                    float gf = d[tt][2*ri+1] + e3.y;
                    float gg = d[tt+4][2*ri] + e3.z;
                    float go = d[tt+4][2*ri+1] + e3.w;
                    float cn = fmaf(sig_fast(gf), c1s[ri][tt], sig_fast(gi) * tanh_fast(gg));
                    c1s[ri][tt] = cn;
                    unsigned short hs = __half_as_ushort(__float2half(sig_fast(go) * tanh_fast(cn)));
                    asm volatile("st.global.cg.u16 [%0], %1;"
                        :: "l"(&g_h1[(size_t)(tile * 128 + r1 + 8 * ri) * 256 + jg]), "h"(hs));
                }
            }
        }
        bt += 16; gbar(tile, bt);
        for (int u = t; u < 4096; u += NT) {       // reload h1 -> chunks 16-31
            int c = u >> 8, rem = u & 255, m = rem >> 1, hi = rem & 1;
            u32 dst = sbase + A_OFF + (16 + c) * 4096 + m * 32 + (((hi ^ (m >> 2)) & 1) << 4);
            CP16(dst, &g_h1[(size_t)(tile * 128 + m) * 256 + c * 16 + hi * 8]);
        }
        CP_COMMIT(); CP_WAITALL();
        __syncthreads();

        // ===== GroupNorm + heads (redundant per CTA; warp w -> rows 16w..16w+15)
        {
            const __half* hc = (const __half*)(smem + HC_OFF);
            uint4 gav = *(const uint4*)(hc + lane * 8);
            uint4 bav4 = *(const uint4*)(hc + 256 + lane * 8);
            uint4 gwv = *(const uint4*)(hc + 512 + lane * 8);
            uint4 bwv4 = *(const uint4*)(hc + 768 + lane * 8);
            float GA[8], BA[8], GW[8], BW[8];
#pragma unroll
            for (int i = 0; i < 4; i++) {
                float2 x;
                x = __half22float2(*(__half2*)&((u32*)&gav)[i]);  GA[2*i]=x.x; GA[2*i+1]=x.y;
                x = __half22float2(*(__half2*)&((u32*)&bav4)[i]); BA[2*i]=x.x; BA[2*i+1]=x.y;
                x = __half22float2(*(__half2*)&((u32*)&gwv)[i]);  GW[2*i]=x.x; GW[2*i+1]=x.y;
                x = __half22float2(*(__half2*)&((u32*)&bwv4)[i]); BW[2*i]=x.x; BW[2*i+1]=x.y;
            }
            for (int rr = 0; rr < 16; rr++) {
                int r = m0 + rr;
                u32 addr = sbase + A_OFF + (16 + (lane >> 1)) * 4096 + r * 32 +
                           ((((lane & 1) ^ (r >> 2)) & 1) << 4);
                u32 hv[4];
                asm volatile("ld.shared.v4.b32 {%0,%1,%2,%3}, [%4];"
                             : "=r"(hv[0]), "=r"(hv[1]), "=r"(hv[2]), "=r"(hv[3]) : "r"(addr));
                float f[8];
#pragma unroll
                for (int i = 0; i < 4; i++) {
                    float2 ff = __half22float2(*(__half2*)&hv[i]);
                    f[2*i] = ff.x; f[2*i+1] = ff.y;
                }
                float sm = 0.f, sq = 0.f;
#pragma unroll
                for (int i = 0; i < 8; i++) { sm += f[i]; sq = fmaf(f[i], f[i], sq); }
#pragma unroll
                for (int off = 1; off < 8; off <<= 1) {
                    sm += __shfl_xor_sync(0xffffffffu, sm, off);
                    sq += __shfl_xor_sync(0xffffffffu, sq, off);
                }
                float mu = sm * (1.f / 64.f);
                float rstd = rsqrtf(sq * (1.f / 64.f) - mu * mu + EPSG);
                float aacc = 0.f, wacc = 0.f;
#pragma unroll
                for (int i = 0; i < 8; i++) {
                    float xn = (f[i] - mu) * rstd;
                    aacc += fmaf(xn, GA[i], BA[i]);
                    wacc += fmaf(xn, GW[i], BW[i]);
                }
#pragma unroll
                for (int off = 1; off < 32; off <<= 1) {
                    aacc += __shfl_xor_sync(0xffffffffu, aacc, off);
                    wacc += __shfl_xor_sync(0xffffffffu, wacc, off);
                }
                if (lane == 0) {
                    float ang = tanh_fast(aacc + bav);
                    float wdt = sig_fast(wacc + bwv);
                    sc[r] = make_float2(ang, wdt);
                    if (rr == q) {
                        float2* op = (float2*)(out + ((size_t)(tile * 128 + r) * T + step) * 2);
                        *op = make_float2(ang, wdt);
                    }
                }
            }
        }
        __syncthreads();
    }
}

extern "C" void kernel_launch(void* const* d_in, const int* in_sizes, int n_in,
                              void* d_out, int out_size) {
    const float* noise    = (const float*)d_in[0];
    const float* W_unpack = (const float*)d_in[1];
    const float* b_unpack = (const float*)d_in[2];
    const float* Wih0     = (const float*)d_in[3];
    const float* Whh0     = (const float*)d_in[4];
    const float* bih0     = (const float*)d_in[5];
    const float* bhh0     = (const float*)d_in[6];
    const float* Wih1     = (const float*)d_in[7];
    const float* Whh1     = (const float*)d_in[8];
    const float* bih1     = (const float*)d_in[9];
    const float* bhh1     = (const float*)d_in[10];
    const float* gamma_a  = (const float*)d_in[11];
    const float* beta_a   = (const float*)d_in[12];
    const float* Wa       = (const float*)d_in[13];
    const float* ba       = (const float*)d_in[14];
    const float* gamma_w  = (const float*)d_in[15];
    const float* beta_w   = (const float*)d_in[16];
    const float* Ww       = (const float*)d_in[17];
    const float* bw       = (const float*)d_in[18];
    (void)in_sizes; (void)n_in;

    int T = out_size / (BB * 2);

    cudaFuncSetAttribute(gen_kernel, cudaFuncAttributeMaxDynamicSharedMemorySize, SMEM_TOTAL);
    prep_kernel<<<512, 256>>>(W_unpack, Wih0, Whh0, bih0, bhh0, Wih1, Whh1, bih1, bhh1,
                              gamma_a, beta_a, Wa, gamma_w, beta_w, Ww);
    gen_kernel<<<NCTA, NT, SMEM_TOTAL>>>(noise, b_unpack, ba, bw, T, (float*)d_out);
}

// round 10
// speedup vs baseline: 2.6981x; 1.1132x over previous
#include <cuda_runtime.h>
#include <cuda_fp16.h>
#include <math.h>
#include <cstdint>

typedef unsigned long long u64;
typedef unsigned int u32;

#define BB 1024
#define TILES 8
#define NT 512
#define NCTA 128
#define EPSG 1e-5f

#define A_OFF  0          // 32 k-chunks * 4096B (chunks 0-15: h0, 16-31: h1)
#define B0_OFF 131072     // 32KB  L0 weight frags
#define B1_OFF 163840     // 64KB  L1 weight frags
#define SC_OFF 229376     // 1KB   coords (128 float2)
#define SMEM_TOTAL 230400

// ---------------- global scratch ----------------
__device__ u64 g_frag0[16 * 4096];   // [q][c16][ntp4][lane32][2]
__device__ u64 g_frag1[16 * 8192];   // [q][c32][ntp4][lane32][2]
__device__ float4 g_epi[256 * 4];    // [j][comp]: bias0 | wa | wb | bias1 (per-gate float4)
__device__ float  g_Wup[128 * 256];
__device__ float  g_hA1[256], g_hA0[256], g_hW1[256], g_hW0[256];
__device__ __half g_h0[TILES * 128 * 256];
__device__ __half g_h1[TILES * 128 * 256];
__device__ float  g_h0f[TILES * 128 * 256];
__device__ unsigned g_barc[TILES];

__device__ __forceinline__ float tanh_fast(float x) {
    float y; asm("tanh.approx.f32 %0, %1;" : "=f"(y) : "f"(x)); return y;
}
__device__ __forceinline__ float sig_fast(float x) {
    return 0.5f * tanh_fast(0.5f * x) + 0.5f;
}
__device__ __forceinline__ u32 smem_u32_of(const void* p) {
    u32 a;
    asm("{ .reg .u64 t; cvta.to.shared.u64 t, %1; cvt.u32.u64 %0, t; }" : "=r"(a) : "l"(p));
    return a;
}
#define CP16(dst, src) \
    asm volatile("cp.async.cg.shared.global [%0], [%1], 16;" :: "r"(dst), "l"(src))
#define CP_COMMIT()  asm volatile("cp.async.commit_group;" ::: "memory")
#define CP_WAITALL() asm volatile("cp.async.wait_all;" ::: "memory")

__device__ __forceinline__ void mma16816(float* d, u32 a0, u32 a1, u32 a2, u32 a3,
                                         u32 b0, u32 b1) {
    asm volatile(
        "mma.sync.aligned.m16n8k16.row.col.f32.f16.f16.f32 "
        "{%0,%1,%2,%3}, {%4,%5,%6,%7}, {%8,%9}, {%0,%1,%2,%3};"
        : "+f"(d[0]), "+f"(d[1]), "+f"(d[2]), "+f"(d[3])
        : "r"(a0), "r"(a1), "r"(a2), "r"(a3), "r"(b0), "r"(b1));
}

__device__ __forceinline__ void gbar(int tile, unsigned target) {
    __syncthreads();
    if (threadIdx.x == 0) {
        asm volatile("red.release.gpu.global.add.u32 [%0], %1;"
                     :: "l"(&g_barc[tile]), "r"(1u) : "memory");
        unsigned v;
        do {
            asm volatile("ld.acquire.gpu.global.u32 %0, [%1];" : "=r"(v) : "l"(&g_barc[tile]));
            if (v < target) __nanosleep(32);
        } while (v < target);
    }
    __syncthreads();
}

__device__ __forceinline__ u64 pack_frag(const float* wr, int k0) {
    __half a = __float2half(wr[k0]),     b = __float2half(wr[k0 + 1]);
    __half c = __float2half(wr[k0 + 8]), d = __float2half(wr[k0 + 9]);
    return (u64)__half_as_ushort(a) | ((u64)__half_as_ushort(b) << 16)
         | ((u64)__half_as_ushort(c) << 32) | ((u64)__half_as_ushort(d) << 48);
}

// ---------------- prep (identical fragment layout to R8) ----------------
__global__ void prep_kernel(const float* __restrict__ W_unpack,
                            const float* __restrict__ Wih0,
                            const float* __restrict__ Whh0,
                            const float* __restrict__ bih0, const float* __restrict__ bhh0,
                            const float* __restrict__ Wih1,
                            const float* __restrict__ Whh1,
                            const float* __restrict__ bih1, const float* __restrict__ bhh1,
                            const float* __restrict__ gamma_a, const float* __restrict__ beta_a,
                            const float* __restrict__ Wa,
                            const float* __restrict__ gamma_w, const float* __restrict__ beta_w,
                            const float* __restrict__ Ww) {
    int i = blockIdx.x * blockDim.x + threadIdx.x;
    if (i < 65536) {
        int q = i >> 12, c = (i >> 8) & 15, ntp = (i >> 6) & 3, lane = (i >> 1) & 31, hs = i & 1;
        int nt = ntp * 2 + hs;
        int nloc = nt * 8 + (lane >> 2);
        int j, gate;
        if (nloc < 32) { j = nloc >> 1; gate = (nloc & 1) ? 1 : 0; }
        else { j = (nloc - 32) >> 1; gate = (nloc & 1) ? 3 : 2; }
        int orig = gate * 256 + q * 16 + j;
        g_frag0[i] = pack_frag(Whh0 + orig * 256, c * 16 + (lane & 3) * 2);
    }
    if (i < 131072) {
        int q = i >> 13, c = (i >> 8) & 31, ntp = (i >> 6) & 3, lane = (i >> 1) & 31, hs = i & 1;
        int nt = ntp * 2 + hs;
        int nloc = nt * 8 + (lane >> 2);
        int j, gate;
        if (nloc < 32) { j = nloc >> 1; gate = (nloc & 1) ? 1 : 0; }
        else { j = (nloc - 32) >> 1; gate = (nloc & 1) ? 3 : 2; }
        int orig = gate * 256 + q * 16 + j;
        const float* src = (c < 16) ? Wih1 : Whh1;
        g_frag1[i] = pack_frag(src + orig * 256, (c & 15) * 16 + (lane & 3) * 2);
    }
    if (i < 1024) {
        int j = i >> 2, comp = i & 3;
        float4 v;
        if (comp == 0)
            v = make_float4(bih0[j] + bhh0[j], bih0[256 + j] + bhh0[256 + j],
                            bih0[512 + j] + bhh0[512 + j], bih0[768 + j] + bhh0[768 + j]);
        else if (comp == 1)
            v = make_float4(Wih0[j * 2], Wih0[(256 + j) * 2],
                            Wih0[(512 + j) * 2], Wih0[(768 + j) * 2]);
        else if (comp == 2)
            v = make_float4(Wih0[j * 2 + 1], Wih0[(256 + j) * 2 + 1],
                            Wih0[(512 + j) * 2 + 1], Wih0[(768 + j) * 2 + 1]);
        else
            v = make_float4(bih1[j] + bhh1[j], bih1[256 + j] + bhh1[256 + j],
                            bih1[512 + j] + bhh1[512 + j], bih1[768 + j] + bhh1[768 + j]);
        g_epi[i] = v;
    }
    if (i < 128 * 256) {
        int k = i >> 8, j = i & 255;
        g_Wup[i] = W_unpack[j * 128 + k];
    }
    if (i < 256) {
        g_hA1[i] = gamma_a[i] * Wa[i];  g_hA0[i] = beta_a[i] * Wa[i];
        g_hW1[i] = gamma_w[i] * Ww[i];  g_hW0[i] = beta_w[i] * Ww[i];
    }
    if (i < TILES) g_barc[i] = 0u;
}

// ---------------- main ----------------
__global__ __launch_bounds__(NT, 1)
void gen_kernel(const float* __restrict__ noise,
                const float* __restrict__ b_unpack,
                const float* __restrict__ ba, const float* __restrict__ bw,
                int T, float* __restrict__ out) {
    extern __shared__ char smem[];
    const u32 sbase = smem_u32_of(smem);
    const int t = threadIdx.x;
    const int w = t >> 5, lane = t & 31;
    const int wq = w & 7;            // M-position (16 rows)
    const int wn = w >> 3;           // N-half (j cols 8*wn .. 8*wn+7 of slice)
    const int tile = blockIdx.x >> 4;
    const int q = blockIdx.x & 15;
    const int m0 = wq * 16;
    float2* sc = (float2*)(smem + SC_OFF);
    const float bav = __ldg(ba), bwv = __ldg(bw);

    if (t < 256) ((float*)sc)[t] = 0.f;

    // weights -> SMEM (fragment-ordered)
    for (int u = t; u < 2048; u += NT)
        CP16(sbase + B0_OFF + u * 16, (const char*)(g_frag0 + q * 4096) + u * 16);
    for (int u = t; u < 4096; u += NT)
        CP16(sbase + B1_OFF + u * 16, (const char*)(g_frag1 + q * 8192) + u * 16);
    CP_COMMIT();

    // noise into A area (scratch), then idea GEMV (slice's 16 j cols)
    float* nf = (float*)(smem + A_OFF);
    for (int i = t; i < 128 * 128; i += NT)
        nf[i] = __ldg(&noise[(size_t)(tile * 128) * 128 + i]);
    __syncthreads();
    if (t < 128) {
        float acc[16];
#pragma unroll
        for (int j = 0; j < 16; j++) acc[j] = __ldg(&b_unpack[q * 16 + j]);
        for (int k = 0; k < 128; k++) {
            float nv = nf[t * 128 + k];
            const float* wr = &g_Wup[k * 256 + q * 16];
#pragma unroll
            for (int j = 0; j < 16; j++) acc[j] = fmaf(nv, __ldg(&wr[j]), acc[j]);
        }
#pragma unroll
        for (int j = 0; j < 16; j++) {
            float v = acc[j];
            float e = (v > 0.f) ? v : (expf(v) - 1.f);
            size_t gi = (size_t)(tile * 128 + t) * 256 + q * 16 + j;
            unsigned short hs = __half_as_ushort(__float2half(e));
            asm volatile("st.global.cg.u16 [%0], %1;" :: "l"(&g_h0[gi]), "h"(hs));
            asm volatile("st.global.cg.f32 [%0], %1;" :: "l"(&g_h0f[gi]), "f"(e));
        }
    }
    CP_WAITALL();
    unsigned bt = 16;
    gbar(tile, bt);

    // c-state init at this thread's (row, j) cells
    const int r1 = m0 + (lane >> 2);
    float c0s[2][2], c1s[2][2];
#pragma unroll
    for (int tt = 0; tt < 2; tt++) {
        int jg = q * 16 + 8 * wn + 4 * tt + (lane & 3);
        c0s[0][tt] = g_h0f[(size_t)(tile * 128 + r1) * 256 + jg];
        c0s[1][tt] = g_h0f[(size_t)(tile * 128 + r1 + 8) * 256 + jg];
        c1s[0][tt] = 0.f; c1s[1][tt] = 0.f;
    }

    // A chunks 0-15 <- h0 (swizzled), 16-31 <- 0
    for (int u = t; u < 4096; u += NT) {
        int c = u >> 8, rem = u & 255, m = rem >> 1, hi = rem & 1;
        u32 dst = sbase + A_OFF + c * 4096 + m * 32 + (((hi ^ (m >> 2)) & 1) << 4);
        CP16(dst, &g_h0[(size_t)(tile * 128 + m) * 256 + c * 16 + hi * 8]);
    }
    CP_COMMIT();
    {
        uint4 z = make_uint4(0, 0, 0, 0);
        uint4* az = (uint4*)(smem + A_OFF + 65536);
        for (int i = t; i < 4096; i += NT) az[i] = z;
    }
    CP_WAITALL();
    __syncthreads();

    const u32 aBase = sbase + A_OFF + (m0 + (lane & 15)) * 32 +
                      (((lane >> 4) ^ (((lane & 15) >> 2) & 1)) << 4);

    for (int step = 0; step < T; ++step) {
        float dm[4][4];
        // ===== L0 MMA: chunks 0-15 (h0_prev), this warp's N-half =====
#pragma unroll
        for (int n = 0; n < 4; n++) { dm[n][0]=dm[n][1]=dm[n][2]=dm[n][3]=0.f; }
#pragma unroll
        for (int c = 0; c < 16; c++) {
            u32 a0, a1, a2, a3;
            asm volatile("ldmatrix.sync.aligned.m8n8.x4.shared.b16 {%0,%1,%2,%3}, [%4];"
                         : "=r"(a0), "=r"(a1), "=r"(a2), "=r"(a3) : "r"(aBase + c * 4096));
#pragma unroll
            for (int pp = 0; pp < 2; pp++) {
                int p = wn + 2 * pp;
                u32 b0, b1, b2, b3;
                asm volatile("ld.shared.v4.b32 {%0,%1,%2,%3}, [%4];"
                             : "=r"(b0), "=r"(b1), "=r"(b2), "=r"(b3)
                             : "r"(sbase + B0_OFF + (c * 4 + p) * 512 + lane * 16));
                mma16816(dm[pp * 2],     a0, a1, a2, a3, b0, b1);
                mma16816(dm[pp * 2 + 1], a0, a1, a2, a3, b2, b3);
            }
        }
        // ===== L0 epilogue =====
        {
            float2 cdA = sc[r1], cdB = sc[r1 + 8];
#pragma unroll
            for (int tt = 0; tt < 2; tt++) {
                int jg = q * 16 + 8 * wn + 4 * tt + (lane & 3);
                float4 e0 = __ldg(&g_epi[jg * 4 + 0]);
                float4 ea = __ldg(&g_epi[jg * 4 + 1]);
                float4 eb = __ldg(&g_epi[jg * 4 + 2]);
#pragma unroll
                for (int ri = 0; ri < 2; ri++) {
                    float2 cd = ri ? cdB : cdA;
                    float gi = dm[tt][2*ri]     + e0.x + ea.x * cd.x + eb.x * cd.y;
                    float gf = dm[tt][2*ri+1]   + e0.y + ea.y * cd.x + eb.y * cd.y;
                    float gg = dm[2+tt][2*ri]   + e0.z + ea.z * cd.x + eb.z * cd.y;
                    float go = dm[2+tt][2*ri+1] + e0.w + ea.w * cd.x + eb.w * cd.y;
                    float cn = fmaf(sig_fast(gf), c0s[ri][tt], sig_fast(gi) * tanh_fast(gg));
                    c0s[ri][tt] = cn;
                    unsigned short hs = __half_as_ushort(__float2half(sig_fast(go) * tanh_fast(cn)));
                    asm volatile("st.global.cg.u16 [%0], %1;"
                        :: "l"(&g_h0[(size_t)(tile * 128 + r1 + 8 * ri) * 256 + jg]), "h"(hs));
                }
            }
        }
        bt += 16; gbar(tile, bt);

        // issue h0 reload -> chunks 0-15 (overlaps L1 part A)
        for (int u = t; u < 4096; u += NT) {
            int c = u >> 8, rem = u & 255, m = rem >> 1, hi = rem & 1;
            u32 dst = sbase + A_OFF + c * 4096 + m * 32 + (((hi ^ (m >> 2)) & 1) << 4);
            CP16(dst, &g_h0[(size_t)(tile * 128 + m) * 256 + c * 16 + hi * 8]);
        }
        CP_COMMIT();

        // ===== L1 MMA part A: chunks 16-31 (h1_prev, already resident) =====
#pragma unroll
        for (int n = 0; n < 4; n++) { dm[n][0]=dm[n][1]=dm[n][2]=dm[n][3]=0.f; }
#pragma unroll
        for (int c = 16; c < 32; c++) {
            u32 a0, a1, a2, a3;
            asm volatile("ldmatrix.sync.aligned.m8n8.x4.shared.b16 {%0,%1,%2,%3}, [%4];"
                         : "=r"(a0), "=r"(a1), "=r"(a2), "=r"(a3) : "r"(aBase + c * 4096));
#pragma unroll
            for (int pp = 0; pp < 2; pp++) {
                int p = wn + 2 * pp;
                u32 b0, b1, b2, b3;
                asm volatile("ld.shared.v4.b32 {%0,%1,%2,%3}, [%4];"
                             : "=r"(b0), "=r"(b1), "=r"(b2), "=r"(b3)
                             : "r"(sbase + B1_OFF + (c * 4 + p) * 512 + lane * 16));
                mma16816(dm[pp * 2],     a0, a1, a2, a3, b0, b1);
                mma16816(dm[pp * 2 + 1], a0, a1, a2, a3, b2, b3);
            }
        }
        CP_WAITALL();
        __syncthreads();
        // ===== L1 MMA part B: chunks 0-15 (h0 new) =====
#pragma unroll
        for (int c = 0; c < 16; c++) {
            u32 a0, a1, a2, a3;
            asm volatile("ldmatrix.sync.aligned.m8n8.x4.shared.b16 {%0,%1,%2,%3}, [%4];"
                         : "=r"(a0), "=r"(a1), "=r"(a2), "=r"(a3) : "r"(aBase + c * 4096));
#pragma unroll
            for (int pp = 0; pp < 2; pp++) {
                int p = wn + 2 * pp;
                u32 b0, b1, b2, b3;
                asm volatile("ld.shared.v4.b32 {%0,%1,%2,%3}, [%4];"
                             : "=r"(b0), "=r"(b1), "=r"(b2), "=r"(b3)
                             : "r"(sbase + B1_OFF + (c * 4 + p) * 512 + lane * 16));
                mma16816(dm[pp * 2],     a0, a1, a2, a3, b0, b1);
                mma16816(dm[pp * 2 + 1], a0, a1, a2, a3, b2, b3);
            }
        }
        // ===== L1 epilogue =====
        {
#pragma unroll
            for (int tt = 0; tt < 2; tt++) {
                int jg = q * 16 + 8 * wn + 4 * tt + (lane & 3);
                float4 e3 = __ldg(&g_epi[jg * 4 + 3]);
#pragma unroll
                for (int ri = 0; ri < 2; ri++) {
                    float gi = dm[tt][2*ri]     + e3.x;
                    float gf = dm[tt][2*ri+1]   + e3.y;
                    float gg = dm[2+tt][2*ri]   + e3.z;
                    float go = dm[2+tt][2*ri+1] + e3.w;
                    float cn = fmaf(sig_fast(gf), c1s[ri][tt], sig_fast(gi) * tanh_fast(gg));
                    c1s[ri][tt] = cn;
                    unsigned short hs = __half_as_ushort(__float2half(sig_fast(go) * tanh_fast(cn)));
                    asm volatile("st.global.cg.u16 [%0], %1;"
                        :: "l"(&g_h1[(size_t)(tile * 128 + r1 + 8 * ri) * 256 + jg]), "h"(hs));
                }
            }
        }
        bt += 16; gbar(tile, bt);

        // issue h1 reload -> chunks 16-31 (overlaps GN)
        for (int u = t; u < 4096; u += NT) {
            int c = u >> 8, rem = u & 255, m = rem >> 1, hi = rem & 1;
            u32 dst = sbase + A_OFF + (16 + c) * 4096 + m * 32 + (((hi ^ (m >> 2)) & 1) << 4);
            CP16(dst, &g_h1[(size_t)(tile * 128 + m) * 256 + c * 16 + hi * 8]);
        }
        CP_COMMIT();

        // ===== GroupNorm + heads: warp w -> rows w*8 .. w*8+7, read h1 from GLOBAL
        {
            float ga[8], bA[8], gw[8], bW[8];
            *(float4*)&ga[0] = __ldg((const float4*)&g_hA1[lane * 8]);
            *(float4*)&ga[4] = __ldg((const float4*)&g_hA1[lane * 8 + 4]);
            *(float4*)&bA[0] = __ldg((const float4*)&g_hA0[lane * 8]);
            *(float4*)&bA[4] = __ldg((const float4*)&g_hA0[lane * 8 + 4]);
            *(float4*)&gw[0] = __ldg((const float4*)&g_hW1[lane * 8]);
            *(float4*)&gw[4] = __ldg((const float4*)&g_hW1[lane * 8 + 4]);
            *(float4*)&bW[0] = __ldg((const float4*)&g_hW0[lane * 8]);
            *(float4*)&bW[4] = __ldg((const float4*)&g_hW0[lane * 8 + 4]);
#pragma unroll 2
            for (int rr = 0; rr < 8; rr++) {
                int r = w * 8 + rr;
                u32 hv[4];
                asm volatile("ld.global.cg.v4.b32 {%0,%1,%2,%3}, [%4];"
                             : "=r"(hv[0]), "=r"(hv[1]), "=r"(hv[2]), "=r"(hv[3])
                             : "l"(&g_h1[(size_t)(tile * 128 + r) * 256 + lane * 8]));
                float f[8];
#pragma unroll
                for (int i = 0; i < 4; i++) {
                    float2 ff = __half22float2(*(__half2*)&hv[i]);
                    f[2*i] = ff.x; f[2*i+1] = ff.y;
                }
                float sm = 0.f, sq = 0.f;
#pragma unroll
                for (int i = 0; i < 8; i++) { sm += f[i]; sq = fmaf(f[i], f[i], sq); }
#pragma unroll
                for (int off = 1; off < 8; off <<= 1) {
                    sm += __shfl_xor_sync(0xffffffffu, sm, off);
                    sq += __shfl_xor_sync(0xffffffffu, sq, off);
                }
                float mu = sm * (1.f / 64.f);
                float rstd = rsqrtf(sq * (1.f / 64.f) - mu * mu + EPSG);
                float aacc = 0.f, wacc = 0.f;
#pragma unroll
                for (int i = 0; i < 8; i++) {
                    float xn = (f[i] - mu) * rstd;
                    aacc += fmaf(xn, ga[i], bA[i]);
                    wacc += fmaf(xn, gw[i], bW[i]);
                }
#pragma unroll
                for (int off = 1; off < 32; off <<= 1) {
                    aacc += __shfl_xor_sync(0xffffffffu, aacc, off);
                    wacc += __shfl_xor_sync(0xffffffffu, wacc, off);
                }
                if (lane == 0) {
                    float ang = tanh_fast(aacc + bav);
                    float wdt = sig_fast(wacc + bwv);
                    sc[r] = make_float2(ang, wdt);
                    if (w == q) {
                        float2* op = (float2*)(out + ((size_t)(tile * 128 + r) * T + step) * 2);
                        *op = make_float2(ang, wdt);
                    }
                }
            }
        }
        CP_WAITALL();
        __syncthreads();
    }
}

extern "C" void kernel_launch(void* const* d_in, const int* in_sizes, int n_in,
                              void* d_out, int out_size) {
    const float* noise    = (const float*)d_in[0];
    const float* W_unpack = (const float*)d_in[1];
    const float* b_unpack = (const float*)d_in[2];
    const float* Wih0     = (const float*)d_in[3];
    const float* Whh0     = (const float*)d_in[4];
    const float* bih0     = (const float*)d_in[5];
    const float* bhh0     = (const float*)d_in[6];
    const float* Wih1     = (const float*)d_in[7];
    const float* Whh1     = (const float*)d_in[8];
    const float* bih1     = (const float*)d_in[9];
    const float* bhh1     = (const float*)d_in[10];
    const float* gamma_a  = (const float*)d_in[11];
    const float* beta_a   = (const float*)d_in[12];
    const float* Wa       = (const float*)d_in[13];
    const float* ba       = (const float*)d_in[14];
    const float* gamma_w  = (const float*)d_in[15];
    const float* beta_w   = (const float*)d_in[16];
    const float* Ww       = (const float*)d_in[17];
    const float* bw       = (const float*)d_in[18];
    (void)in_sizes; (void)n_in;

    int T = out_size / (BB * 2);

    cudaFuncSetAttribute(gen_kernel, cudaFuncAttributeMaxDynamicSharedMemorySize, SMEM_TOTAL);
    prep_kernel<<<512, 256>>>(W_unpack, Wih0, Whh0, bih0, bhh0, Wih1, Whh1, bih1, bhh1,
                              gamma_a, beta_a, Wa, gamma_w, beta_w, Ww);
    gen_kernel<<<NCTA, NT, SMEM_TOTAL>>>(noise, b_unpack, ba, bw, T, (float*)d_out);
}

// round 11
// speedup vs baseline: 3.6062x; 1.3366x over previous
#include <cuda_runtime.h>
#include <cuda_fp16.h>
#include <math.h>
#include <cstdint>

typedef unsigned long long u64;
typedef unsigned int u32;

#define BB 1024
#define TILES 8
#define NT 512
#define NCTA 128
#define EPSG 1e-5f

#define A_OFF  0          // 32 k-chunks * 4096B (0-15: h0, 16-31: h1); chunk0 doubles as staging
#define B0_OFF 131072
#define B1_OFF 163840
#define SMEM_TOTAL 229376

// ---------------- global scratch ----------------
__device__ u64 g_frag0[16 * 4096];
__device__ u64 g_frag1[16 * 8192];
__device__ float4 g_epi[1024];
__device__ float  g_Wup[128 * 256];
__device__ float  g_hA1[256], g_hA0[256], g_hW1[256], g_hW0[256];
__device__ __half g_h0p[TILES * 16 * 128 * 16];   // packed slices [tile][q][row][16]
__device__ __half g_h1p[TILES * 16 * 128 * 16];
__device__ float  g_h0f[TILES * 128 * 256];
__device__ float2 g_coord[TILES * 128];
__device__ unsigned g_barc[TILES * 32];           // padded: one counter per 128B

__device__ __forceinline__ float tanh_fast(float x) {
    float y; asm("tanh.approx.f32 %0, %1;" : "=f"(y) : "f"(x)); return y;
}
__device__ __forceinline__ float sig_fast(float x) {
    return 0.5f * tanh_fast(0.5f * x) + 0.5f;
}
__device__ __forceinline__ u32 smem_u32_of(const void* p) {
    u32 a;
    asm("{ .reg .u64 t; cvta.to.shared.u64 t, %1; cvt.u32.u64 %0, t; }" : "=r"(a) : "l"(p));
    return a;
}
#define CP16(dst, src) \
    asm volatile("cp.async.cg.shared.global [%0], [%1], 16;" :: "r"(dst), "l"(src))
#define CP_COMMIT()  asm volatile("cp.async.commit_group;" ::: "memory")
#define CP_WAITALL() asm volatile("cp.async.wait_all;" ::: "memory")

__device__ __forceinline__ void mma16816(float* d, u32 a0, u32 a1, u32 a2, u32 a3,
                                         u32 b0, u32 b1) {
    asm volatile(
        "mma.sync.aligned.m16n8k16.row.col.f32.f16.f16.f32 "
        "{%0,%1,%2,%3}, {%4,%5,%6,%7}, {%8,%9}, {%0,%1,%2,%3};"
        : "+f"(d[0]), "+f"(d[1]), "+f"(d[2]), "+f"(d[3])
        : "r"(a0), "r"(a1), "r"(a2), "r"(a3), "r"(b0), "r"(b1));
}

__device__ __forceinline__ void bar_arrive(int tile) {
    __syncthreads();
    if (threadIdx.x == 0)
        asm volatile("red.release.gpu.global.add.u32 [%0], %1;"
                     :: "l"(&g_barc[tile * 32]), "r"(1u) : "memory");
}
__device__ __forceinline__ void bar_wait(int tile, unsigned target) {
    if (threadIdx.x == 0) {
        unsigned v;
        do {
            asm volatile("ld.acquire.gpu.global.u32 %0, [%1];"
                         : "=r"(v) : "l"(&g_barc[tile * 32]));
        } while (v < target);
    }
    __syncthreads();
}

__device__ __forceinline__ u64 pack_frag(const float* wr, int k0) {
    __half a = __float2half(wr[k0]),     b = __float2half(wr[k0 + 1]);
    __half c = __float2half(wr[k0 + 8]), d = __float2half(wr[k0 + 9]);
    return (u64)__half_as_ushort(a) | ((u64)__half_as_ushort(b) << 16)
         | ((u64)__half_as_ushort(c) << 32) | ((u64)__half_as_ushort(d) << 48);
}

// ---------------- prep ----------------
__global__ void prep_kernel(const float* __restrict__ W_unpack,
                            const float* __restrict__ Wih0,
                            const float* __restrict__ Whh0,
                            const float* __restrict__ bih0, const float* __restrict__ bhh0,
                            const float* __restrict__ Wih1,
                            const float* __restrict__ Whh1,
                            const float* __restrict__ bih1, const float* __restrict__ bhh1,
                            const float* __restrict__ gamma_a, const float* __restrict__ beta_a,
                            const float* __restrict__ Wa,
                            const float* __restrict__ gamma_w, const float* __restrict__ beta_w,
                            const float* __restrict__ Ww) {
    int i = blockIdx.x * blockDim.x + threadIdx.x;
    if (i < 65536) {
        int q = i >> 12, c = (i >> 8) & 15, ntp = (i >> 6) & 3, lane = (i >> 1) & 31, hs = i & 1;
        int nt = ntp * 2 + hs;
        int nloc = nt * 8 + (lane >> 2);
        int j, gate;
        if (nloc < 32) { j = nloc >> 1; gate = (nloc & 1) ? 1 : 0; }
        else { j = (nloc - 32) >> 1; gate = (nloc & 1) ? 3 : 2; }
        int orig = gate * 256 + q * 16 + j;
        g_frag0[i] = pack_frag(Whh0 + orig * 256, c * 16 + (lane & 3) * 2);
    }
    if (i < 131072) {
        int q = i >> 13, c = (i >> 8) & 31, ntp = (i >> 6) & 3, lane = (i >> 1) & 31, hs = i & 1;
        int nt = ntp * 2 + hs;
        int nloc = nt * 8 + (lane >> 2);
        int j, gate;
        if (nloc < 32) { j = nloc >> 1; gate = (nloc & 1) ? 1 : 0; }
        else { j = (nloc - 32) >> 1; gate = (nloc & 1) ? 3 : 2; }
        int orig = gate * 256 + q * 16 + j;
        const float* src = (c < 16) ? Wih1 : Whh1;
        g_frag1[i] = pack_frag(src + orig * 256, (c & 15) * 16 + (lane & 3) * 2);
    }
    if (i < 1024) {
        int j = i >> 2, comp = i & 3;
        float4 v;
        if (comp == 0)
            v = make_float4(bih0[j] + bhh0[j], bih0[256 + j] + bhh0[256 + j],
                            bih0[512 + j] + bhh0[512 + j], bih0[768 + j] + bhh0[768 + j]);
        else if (comp == 1)
            v = make_float4(Wih0[j * 2], Wih0[(256 + j) * 2],
                            Wih0[(512 + j) * 2], Wih0[(768 + j) * 2]);
        else if (comp == 2)
            v = make_float4(Wih0[j * 2 + 1], Wih0[(256 + j) * 2 + 1],
                            Wih0[(512 + j) * 2 + 1], Wih0[(768 + j) * 2 + 1]);
        else
            v = make_float4(bih1[j] + bhh1[j], bih1[256 + j] + bhh1[256 + j],
                            bih1[512 + j] + bhh1[512 + j], bih1[768 + j] + bhh1[768 + j]);
        g_epi[i] = v;
    }
    if (i < 128 * 256) {
        int k = i >> 8, j = i & 255;
        g_Wup[i] = W_unpack[j * 128 + k];
    }
    if (i < 256) {
        g_hA1[i] = gamma_a[i] * Wa[i];  g_hA0[i] = beta_a[i] * Wa[i];
        g_hW1[i] = gamma_w[i] * Ww[i];  g_hW0[i] = beta_w[i] * Ww[i];
    }
    if (i < TILES * 128) g_coord[i] = make_float2(0.f, 0.f);
    if (i < TILES) g_barc[i * 32] = 0u;
}

// ---------------- main ----------------
__global__ __launch_bounds__(NT, 1)
void gen_kernel(const float* __restrict__ noise,
                const float* __restrict__ b_unpack,
                const float* __restrict__ ba, const float* __restrict__ bw,
                int T, float* __restrict__ out) {
    extern __shared__ char smem[];
    const u32 sbase = smem_u32_of(smem);
    const int t = threadIdx.x;
    const int w = t >> 5, lane = t & 31;
    const int wq = w & 7;
    const int wn = w >> 3;
    const int tile = blockIdx.x >> 4;
    const int q = blockIdx.x & 15;
    const int m0 = wq * 16;
    const int r1 = m0 + (lane >> 2);
    const float bav = __ldg(ba), bwv = __ldg(bw);

    const u32 stage0 = sbase + A_OFF;            // h0-slice staging (chunk 0 area)
    const u32 stage1 = sbase + A_OFF + 65536;    // h1-slice staging (chunk 16 area)
    __half* h0slice = (__half*)&g_h0p[(size_t)(tile * 16 + q) * 2048];
    __half* h1slice = (__half*)&g_h1p[(size_t)(tile * 16 + q) * 2048];

    // weights -> SMEM (fragment-ordered)
    for (int u = t; u < 2048; u += NT)
        CP16(sbase + B0_OFF + u * 16, (const char*)(g_frag0 + q * 4096) + u * 16);
    for (int u = t; u < 4096; u += NT)
        CP16(sbase + B1_OFF + u * 16, (const char*)(g_frag1 + q * 8192) + u * 16);
    CP_COMMIT();

    // noise into A area (scratch), idea GEMV for own 16 j-cols
    float* nf = (float*)(smem + A_OFF);
    for (int i = t; i < 128 * 128; i += NT)
        nf[i] = __ldg(&noise[(size_t)(tile * 128) * 128 + i]);
    __syncthreads();
    float ideav[16];
    if (t < 128) {
#pragma unroll
        for (int j = 0; j < 16; j++) ideav[j] = __ldg(&b_unpack[q * 16 + j]);
        for (int k = 0; k < 128; k++) {
            float nv = nf[t * 128 + k];
            const float* wr = &g_Wup[k * 256 + q * 16];
#pragma unroll
            for (int j = 0; j < 16; j++) ideav[j] = fmaf(nv, __ldg(&wr[j]), ideav[j]);
        }
    }
    __syncthreads();   // nf reads done before staging overwrites A area
    if (t < 128) {
#pragma unroll
        for (int j = 0; j < 16; j++) {
            float v = ideav[j];
            float e = (v > 0.f) ? v : (expf(v) - 1.f);
            asm volatile("st.global.cg.f32 [%0], %1;"
                :: "l"(&g_h0f[(size_t)(tile * 128 + t) * 256 + q * 16 + j]), "f"(e));
            unsigned short hs = __half_as_ushort(__float2half(e));
            asm volatile("st.shared.u16 [%0], %1;" :: "r"(stage0 + (t * 16 + j) * 2), "h"(hs));
        }
    }
    __syncthreads();
    if (t < 256) {
        u32 v0, v1, v2, v3;
        asm volatile("ld.shared.v4.b32 {%0,%1,%2,%3}, [%4];"
                     : "=r"(v0), "=r"(v1), "=r"(v2), "=r"(v3) : "r"(stage0 + t * 16));
        asm volatile("st.global.cg.v4.b32 [%0], {%1,%2,%3,%4};"
                     :: "l"((char*)h0slice + t * 16), "r"(v0), "r"(v1), "r"(v2), "r"(v3));
    }
    CP_WAITALL();          // weights landed
    bar_arrive(tile);      // E0: h0 published
    bar_wait(tile, 16);

    // c-state init
    float c0s[2][2], c1s[2][2];
#pragma unroll
    for (int tt = 0; tt < 2; tt++) {
        int jg = q * 16 + 8 * wn + 4 * tt + (lane & 3);
        c0s[0][tt] = g_h0f[(size_t)(tile * 128 + r1) * 256 + jg];
        c0s[1][tt] = g_h0f[(size_t)(tile * 128 + r1 + 8) * 256 + jg];
        c1s[0][tt] = 0.f; c1s[1][tt] = 0.f;
    }

    // A chunks 0-15 <- h0 (packed slices), 16-31 <- 0
    for (int u = t; u < 4096; u += NT) {
        int c = u >> 8, rem = u & 255, m = rem >> 1, hi = rem & 1;
        u32 dst = sbase + A_OFF + c * 4096 + m * 32 + (((hi ^ (m >> 2)) & 1) << 4);
        CP16(dst, &g_h0p[(size_t)((tile * 16 + c) * 128 + m) * 16 + hi * 8]);
    }
    CP_COMMIT();
    {
        uint4 z = make_uint4(0, 0, 0, 0);
        uint4* az = (uint4*)(smem + A_OFF + 65536);
        for (int i = t; i < 4096; i += NT) az[i] = z;
    }
    CP_WAITALL();
    __syncthreads();

    const u32 aBase = sbase + A_OFF + (m0 + (lane & 15)) * 32 +
                      (((lane >> 4) ^ (((lane & 15) >> 2) & 1)) << 4);

    for (int step = 0; step < T; ++step) {
        float dm[4][4];
        // ===== L0 MMA: chunks 0-15 (h0_prev) =====
#pragma unroll
        for (int n = 0; n < 4; n++) { dm[n][0]=dm[n][1]=dm[n][2]=dm[n][3]=0.f; }
#pragma unroll
        for (int c = 0; c < 16; c++) {
            u32 a0, a1, a2, a3;
            asm volatile("ldmatrix.sync.aligned.m8n8.x4.shared.b16 {%0,%1,%2,%3}, [%4];"
                         : "=r"(a0), "=r"(a1), "=r"(a2), "=r"(a3) : "r"(aBase + c * 4096));
#pragma unroll
            for (int pp = 0; pp < 2; pp++) {
                int p = wn + 2 * pp;
                u32 b0, b1, b2, b3;
                asm volatile("ld.shared.v4.b32 {%0,%1,%2,%3}, [%4];"
                             : "=r"(b0), "=r"(b1), "=r"(b2), "=r"(b3)
                             : "r"(sbase + B0_OFF + (c * 4 + p) * 512 + lane * 16));
                mma16816(dm[pp * 2],     a0, a1, a2, a3, b0, b1);
                mma16816(dm[pp * 2 + 1], a0, a1, a2, a3, b2, b3);
            }
        }
        // coords of previous step (event C_{s-1}; E0 for s=0)
        bar_wait(tile, 16u * (3 * step + 1));
        float2 cdA, cdB;
        asm volatile("ld.global.cg.v2.f32 {%0,%1}, [%2];"
                     : "=f"(cdA.x), "=f"(cdA.y) : "l"(&g_coord[tile * 128 + r1]));
        asm volatile("ld.global.cg.v2.f32 {%0,%1}, [%2];"
                     : "=f"(cdB.x), "=f"(cdB.y) : "l"(&g_coord[tile * 128 + r1 + 8]));
        // ===== L0 epilogue -> stage slice =====
#pragma unroll
        for (int tt = 0; tt < 2; tt++) {
            int jg = q * 16 + 8 * wn + 4 * tt + (lane & 3);
            int jloc = 8 * wn + 4 * tt + (lane & 3);
            float4 e0 = __ldg(&g_epi[jg * 4 + 0]);
            float4 ea = __ldg(&g_epi[jg * 4 + 1]);
            float4 eb = __ldg(&g_epi[jg * 4 + 2]);
#pragma unroll
            for (int ri = 0; ri < 2; ri++) {
                float2 cd = ri ? cdB : cdA;
                float gi = dm[tt][2*ri]     + e0.x + ea.x * cd.x + eb.x * cd.y;
                float gf = dm[tt][2*ri+1]   + e0.y + ea.y * cd.x + eb.y * cd.y;
                float gg = dm[2+tt][2*ri]   + e0.z + ea.z * cd.x + eb.z * cd.y;
                float go = dm[2+tt][2*ri+1] + e0.w + ea.w * cd.x + eb.w * cd.y;
                float cn = fmaf(sig_fast(gf), c0s[ri][tt], sig_fast(gi) * tanh_fast(gg));
                c0s[ri][tt] = cn;
                unsigned short hs = __half_as_ushort(__float2half(sig_fast(go) * tanh_fast(cn)));
                asm volatile("st.shared.u16 [%0], %1;"
                             :: "r"(stage0 + ((r1 + 8 * ri) * 16 + jloc) * 2), "h"(hs));
            }
        }
        __syncthreads();
        if (t < 256) {
            u32 v0, v1, v2, v3;
            asm volatile("ld.shared.v4.b32 {%0,%1,%2,%3}, [%4];"
                         : "=r"(v0), "=r"(v1), "=r"(v2), "=r"(v3) : "r"(stage0 + t * 16));
            asm volatile("st.global.cg.v4.b32 [%0], {%1,%2,%3,%4};"
                         :: "l"((char*)h0slice + t * 16), "r"(v0), "r"(v1), "r"(v2), "r"(v3));
        }
        bar_arrive(tile);   // event A: h0new published

        // ===== L1 partA: chunks 16-31 (h1_prev, resident) =====
#pragma unroll
        for (int n = 0; n < 4; n++) { dm[n][0]=dm[n][1]=dm[n][2]=dm[n][3]=0.f; }
#pragma unroll
        for (int c = 16; c < 32; c++) {
            u32 a0, a1, a2, a3;
            asm volatile("ldmatrix.sync.aligned.m8n8.x4.shared.b16 {%0,%1,%2,%3}, [%4];"
                         : "=r"(a0), "=r"(a1), "=r"(a2), "=r"(a3) : "r"(aBase + c * 4096));
#pragma unroll
            for (int pp = 0; pp < 2; pp++) {
                int p = wn + 2 * pp;
                u32 b0, b1, b2, b3;
                asm volatile("ld.shared.v4.b32 {%0,%1,%2,%3}, [%4];"
                             : "=r"(b0), "=r"(b1), "=r"(b2), "=r"(b3)
                             : "r"(sbase + B1_OFF + (c * 4 + p) * 512 + lane * 16));
                mma16816(dm[pp * 2],     a0, a1, a2, a3, b0, b1);
                mma16816(dm[pp * 2 + 1], a0, a1, a2, a3, b2, b3);
            }
        }
        bar_wait(tile, 16u * (3 * step + 2));
        // reload h0new -> chunks 0-15
        for (int u = t; u < 4096; u += NT) {
            int c = u >> 8, rem = u & 255, m = rem >> 1, hi = rem & 1;
            u32 dst = sbase + A_OFF + c * 4096 + m * 32 + (((hi ^ (m >> 2)) & 1) << 4);
            CP16(dst, &g_h0p[(size_t)((tile * 16 + c) * 128 + m) * 16 + hi * 8]);
        }
        CP_COMMIT(); CP_WAITALL();
        __syncthreads();
        // ===== L1 partB: chunks 0-15 (h0 new) =====
#pragma unroll
        for (int c = 0; c < 16; c++) {
            u32 a0, a1, a2, a3;
            asm volatile("ldmatrix.sync.aligned.m8n8.x4.shared.b16 {%0,%1,%2,%3}, [%4];"
                         : "=r"(a0), "=r"(a1), "=r"(a2), "=r"(a3) : "r"(aBase + c * 4096));
#pragma unroll
            for (int pp = 0; pp < 2; pp++) {
                int p = wn + 2 * pp;
                u32 b0, b1, b2, b3;
                asm volatile("ld.shared.v4.b32 {%0,%1,%2,%3}, [%4];"
                             : "=r"(b0), "=r"(b1), "=r"(b2), "=r"(b3)
                             : "r"(sbase + B1_OFF + (c * 4 + p) * 512 + lane * 16));
                mma16816(dm[pp * 2],     a0, a1, a2, a3, b0, b1);
                mma16816(dm[pp * 2 + 1], a0, a1, a2, a3, b2, b3);
            }
        }
        // ===== L1 epilogue -> stage slice (chunk16 area; partA reads done) =====
#pragma unroll
        for (int tt = 0; tt < 2; tt++) {
            int jg = q * 16 + 8 * wn + 4 * tt + (lane & 3);
            int jloc = 8 * wn + 4 * tt + (lane & 3);
            float4 e3 = __ldg(&g_epi[jg * 4 + 3]);
#pragma unroll
            for (int ri = 0; ri < 2; ri++) {
                float gi = dm[tt][2*ri]     + e3.x;
                float gf = dm[tt][2*ri+1]   + e3.y;
                float gg = dm[2+tt][2*ri]   + e3.z;
                float go = dm[2+tt][2*ri+1] + e3.w;
                float cn = fmaf(sig_fast(gf), c1s[ri][tt], sig_fast(gi) * tanh_fast(gg));
                c1s[ri][tt] = cn;
                unsigned short hs = __half_as_ushort(__float2half(sig_fast(go) * tanh_fast(cn)));
                asm volatile("st.shared.u16 [%0], %1;"
                             :: "r"(stage1 + ((r1 + 8 * ri) * 16 + jloc) * 2), "h"(hs));
            }
        }
        __syncthreads();
        if (t < 256) {
            u32 v0, v1, v2, v3;
            asm volatile("ld.shared.v4.b32 {%0,%1,%2,%3}, [%4];"
                         : "=r"(v0), "=r"(v1), "=r"(v2), "=r"(v3) : "r"(stage1 + t * 16));
            asm volatile("st.global.cg.v4.b32 [%0], {%1,%2,%3,%4};"
                         :: "l"((char*)h1slice + t * 16), "r"(v0), "r"(v1), "r"(v2), "r"(v3));
        }
        bar_arrive(tile);   // event B: h1new published
        bar_wait(tile, 16u * (3 * step + 3));

        // reload h1new -> chunks 16-31 (overlaps GN)
        for (int u = t; u < 4096; u += NT) {
            int c = u >> 8, rem = u & 255, m = rem >> 1, hi = rem & 1;
            u32 dst = sbase + A_OFF + (16 + c) * 4096 + m * 32 + (((hi ^ (m >> 2)) & 1) << 4);
            CP16(dst, &g_h1p[(size_t)((tile * 16 + c) * 128 + m) * 16 + hi * 8]);
        }
        CP_COMMIT();

        // ===== GN + heads: own 8 rows only (warp i -> row q*8+i) =====
        if (w < 8) {
            int ro = q * 8 + w;
            u32 hv[4];
            asm volatile("ld.global.cg.v4.b32 {%0,%1,%2,%3}, [%4];"
                         : "=r"(hv[0]), "=r"(hv[1]), "=r"(hv[2]), "=r"(hv[3])
                         : "l"(&g_h1p[(size_t)((tile * 16 + (lane >> 1)) * 128 + ro) * 16 + (lane & 1) * 8]));
            float f[8];
#pragma unroll
            for (int i = 0; i < 4; i++) {
                float2 ff = __half22float2(*(__half2*)&hv[i]);
                f[2*i] = ff.x; f[2*i+1] = ff.y;
            }
            float sm = 0.f, sq = 0.f;
#pragma unroll
            for (int i = 0; i < 8; i++) { sm += f[i]; sq = fmaf(f[i], f[i], sq); }
#pragma unroll
            for (int off = 1; off < 8; off <<= 1) {
                sm += __shfl_xor_sync(0xffffffffu, sm, off);
                sq += __shfl_xor_sync(0xffffffffu, sq, off);
            }
            float mu = sm * (1.f / 64.f);
            float rstd = rsqrtf(sq * (1.f / 64.f) - mu * mu + EPSG);
            float aacc = 0.f, wacc = 0.f;
#pragma unroll
            for (int i = 0; i < 8; i++) {
                int cidx = lane * 8 + i;
                float xn = (f[i] - mu) * rstd;
                aacc += fmaf(xn, __ldg(&g_hA1[cidx]), __ldg(&g_hA0[cidx]));
                wacc += fmaf(xn, __ldg(&g_hW1[cidx]), __ldg(&g_hW0[cidx]));
            }
#pragma unroll
            for (int off = 1; off < 32; off <<= 1) {
                aacc += __shfl_xor_sync(0xffffffffu, aacc, off);
                wacc += __shfl_xor_sync(0xffffffffu, wacc, off);
            }
            if (lane == 0) {
                float ang = tanh_fast(aacc + bav);
                float wdt = sig_fast(wacc + bwv);
                asm volatile("st.global.cg.v2.f32 [%0], {%1,%2};"
                             :: "l"(&g_coord[tile * 128 + ro]), "f"(ang), "f"(wdt));
                float2* op = (float2*)(out + ((size_t)(tile * 128 + ro) * T + step) * 2);
                *op = make_float2(ang, wdt);
            }
        }
        bar_arrive(tile);   // event C: coords published
        CP_WAITALL();
        __syncthreads();
    }
}

extern "C" void kernel_launch(void* const* d_in, const int* in_sizes, int n_in,
                              void* d_out, int out_size) {
    const float* noise    = (const float*)d_in[0];
    const float* W_unpack = (const float*)d_in[1];
    const float* b_unpack = (const float*)d_in[2];
    const float* Wih0     = (const float*)d_in[3];
    const float* Whh0     = (const float*)d_in[4];
    const float* bih0     = (const float*)d_in[5];
    const float* bhh0     = (const float*)d_in[6];
    const float* Wih1     = (const float*)d_in[7];
    const float* Whh1     = (const float*)d_in[8];
    const float* bih1     = (const float*)d_in[9];
    const float* bhh1     = (const float*)d_in[10];
    const float* gamma_a  = (const float*)d_in[11];
    const float* beta_a   = (const float*)d_in[12];
    const float* Wa       = (const float*)d_in[13];
    const float* ba       = (const float*)d_in[14];
    const float* gamma_w  = (const float*)d_in[15];
    const float* beta_w   = (const float*)d_in[16];
    const float* Ww       = (const float*)d_in[17];
    const float* bw       = (const float*)d_in[18];
    (void)in_sizes; (void)n_in;

    int T = out_size / (BB * 2);

    cudaFuncSetAttribute(gen_kernel, cudaFuncAttributeMaxDynamicSharedMemorySize, SMEM_TOTAL);
    prep_kernel<<<512, 256>>>(W_unpack, Wih0, Whh0, bih0, bhh0, Wih1, Whh1, bih1, bhh1,
                              gamma_a, beta_a, Wa, gamma_w, beta_w, Ww);
    gen_kernel<<<NCTA, NT, SMEM_TOTAL>>>(noise, b_unpack, ba, bw, T, (float*)d_out);
}